// round 17
// baseline (speedup 1.0000x reference)
#include <cuda_runtime.h>
#include <cstddef>

#define N_ROWS 8192
#define N_COLS 8192
#define THREADS 320          // 5 groups x 64 threads
#define NWARP (THREADS / 32) // 10
#define N_STEPS 100
#define HALF_STEPS 50

// Cross-kernel scratch (device globals: allowed; no allocation).
__device__ float g_loss[N_STEPS][N_ROWS];   // losses[step][row]
__device__ float g_aux[2][N_ROWS];          // [0]=rmin, [1]=rmax per row

__device__ __forceinline__ float shfl_add(float v) {
    #pragma unroll
    for (int o = 16; o; o >>= 1) v += __shfl_xor_sync(0xFFFFFFFFu, v, o);
    return v;
}

// One step, two elements. W is a PTX decimal literal string for 1/i.
// Row pre-scaled by K=12750/R so u_i = ax * (1/i)  (validated in R10).
// rr = fma(ax, W_imm, M) = M + round(u)  [FFMA-imm rt1]
// rr = min(rr, cb), cb = M+127 (x>=0) / M+128 (x<0)   [alu]
// nq = M2 - rr (packed, exact)                         [fma rt2]
// dd = fma(ax, W_imm, nq) = u - q  [FFMA-imm rt1]
// acc += dd*dd (packed)                                [fma rt2]
#define STEP(ACC, W) \
    asm("{\n\t" \
        ".reg .f32 r0,r1,d0,d1;\n\t" \
        ".reg .b64 rr,nq,dd;\n\t" \
        "fma.rn.f32 r0, %1, " W ", %6;\n\t" \
        "fma.rn.f32 r1, %2, " W ", %6;\n\t" \
        "min.f32 r0, r0, %3;\n\t" \
        "min.f32 r1, r1, %4;\n\t" \
        "mov.b64 rr, {r0,r1};\n\t" \
        "sub.rn.f32x2 nq, %5, rr;\n\t" \
        "mov.b64 {d0,d1}, nq;\n\t" \
        "fma.rn.f32 d0, %1, " W ", d0;\n\t" \
        "fma.rn.f32 d1, %2, " W ", d1;\n\t" \
        "mov.b64 dd, {d0,d1};\n\t" \
        "fma.rn.f32x2 %0, dd, dd, %0;\n\t" \
        "}" \
        : "+l"(ACC) \
        : "f"(ax0), "f"(ax1), "f"(cb0), "f"(cb1), "l"(M2), "f"(Mf))

#define RED(A, J) do { \
    float lo, hi; \
    asm("mov.b64 {%0,%1}, %2;" : "=f"(lo), "=f"(hi) : "l"(A)); \
    float v = lo + hi; \
    v = shfl_add(v); \
    if (lane == 0) partial[warp][J] = v; \
} while (0)

#define MAKE_RUNNER(NAME, S1,S2,S3,S4,S5,S6,S7,S8,S9,S10) \
__device__ __forceinline__ void NAME(const float2* __restrict__ row2, int l64, \
        unsigned long long M2, float Mf, int warp, int lane, float (*partial)[10]) { \
    unsigned long long a0=0,a1=0,a2=0,a3=0,a4=0,a5=0,a6=0,a7=0,a8=0,a9=0; \
    _Pragma("unroll 2") \
    for (int k = 0; k < 64; k++) { \
        float2 xv = row2[l64 + (k << 6)]; \
        unsigned xb0 = __float_as_uint(xv.x); \
        unsigned xb1 = __float_as_uint(xv.y); \
        float ax0 = __uint_as_float(xb0 & 0x7FFFFFFFu); \
        float ax1 = __uint_as_float(xb1 & 0x7FFFFFFFu); \
        float cb0 = __uint_as_float(0x4B40007Fu + (xb0 >> 31)); \
        float cb1 = __uint_as_float(0x4B40007Fu + (xb1 >> 31)); \
        STEP(a0, S1); STEP(a1, S2); STEP(a2, S3); STEP(a3, S4); STEP(a4, S5); \
        STEP(a5, S6); STEP(a6, S7); STEP(a7, S8); STEP(a8, S9); STEP(a9, S10); \
    } \
    RED(a0, 0); RED(a1, 1); RED(a2, 2); RED(a3, 3); RED(a4, 4); \
    RED(a5, 5); RED(a6, 6); RED(a7, 7); RED(a8, 8); RED(a9, 9); \
}

// 10 runners x 10 steps = steps 1..100; W strings are decimal 1/i (>=13 sig
// digits -> exact fp32 after PTX double parse + RN convert).
MAKE_RUNNER(run_s0, "1.0","0.5","0.33333333333333","0.25","0.2","0.16666666666667","0.14285714285714","0.125","0.11111111111111","0.1")
MAKE_RUNNER(run_s1, "0.090909090909091","0.083333333333333","0.076923076923077","0.071428571428571","0.066666666666667","0.0625","0.058823529411765","0.055555555555556","0.052631578947368","0.05")
MAKE_RUNNER(run_s2, "0.047619047619048","0.045454545454545","0.043478260869565","0.041666666666667","0.04","0.038461538461538","0.037037037037037","0.035714285714286","0.034482758620690","0.033333333333333")
MAKE_RUNNER(run_s3, "0.032258064516129","0.03125","0.030303030303030","0.029411764705882","0.028571428571429","0.027777777777778","0.027027027027027","0.026315789473684","0.025641025641026","0.025")
MAKE_RUNNER(run_s4, "0.024390243902439","0.023809523809524","0.023255813953488","0.022727272727273","0.022222222222222","0.021739130434783","0.021276595744681","0.020833333333333","0.020408163265306","0.02")
MAKE_RUNNER(run_s5, "0.019607843137255","0.019230769230769","0.018867924528302","0.018518518518519","0.018181818181818","0.017857142857143","0.017543859649123","0.017241379310345","0.016949152542373","0.016666666666667")
MAKE_RUNNER(run_s6, "0.016393442622951","0.016129032258065","0.015873015873016","0.015625","0.015384615384615","0.015151515151515","0.014925373134328","0.014705882352941","0.014492753623188","0.014285714285714")
MAKE_RUNNER(run_s7, "0.014084507042254","0.013888888888889","0.013698630136986","0.013513513513514","0.013333333333333","0.013157894736842","0.012987012987013","0.012820512820513","0.012658227848101","0.0125")
MAKE_RUNNER(run_s8, "0.012345679012346","0.012195121951220","0.012048192771084","0.011904761904762","0.011764705882353","0.011627906976744","0.011494252873563","0.011363636363636","0.011235955056180","0.011111111111111")
MAKE_RUNNER(run_s9, "0.010989010989011","0.010869565217391","0.010752688172043","0.010638297872340","0.010526315789474","0.010416666666667","0.010309278350515","0.010204081632653","0.010101010101010","0.01")

// Kernel 1: grid (N_ROWS, 2). blockIdx.y selects which 50 steps this block owns.
__global__ __launch_bounds__(THREADS)
void mse_losses_kernel(const float* __restrict__ x, unsigned long long M2) {
    __shared__ float row_sm[N_COLS];
    __shared__ float s2k[HALF_STEPS];      // scale^2 / 8192 for this half
    __shared__ float partial[NWARP][10];   // per-warp partials (group-local idx)
    __shared__ float red_min[NWARP], red_max[NWARP];
    __shared__ float Rsh, Ksh;

    const int row  = blockIdx.x;
    const int half = blockIdx.y;
    const int tid  = threadIdx.x;
    const int warp = tid >> 5;
    const int lane = tid & 31;
    const float Mf = 12582912.0f;          // 1.5 * 2^23
    const float* xr = x + (size_t)row * N_COLS;

    // ---- Phase A: load row to smem, compute row min/max ----
    float mn = 3.0e38f, mx = -3.0e38f;
    const float4* xr4 = (const float4*)xr;
    float4* row4 = (float4*)row_sm;
    #pragma unroll
    for (int k = 0; k < 7; k++) {
        int idx = tid + k * THREADS;
        if (idx < N_COLS / 4) {
            float4 v = xr4[idx];
            row4[idx] = v;
            mn = fminf(mn, fminf(fminf(v.x, v.y), fminf(v.z, v.w)));
            mx = fmaxf(mx, fmaxf(fmaxf(v.x, v.y), fmaxf(v.z, v.w)));
        }
    }
    #pragma unroll
    for (int o = 16; o; o >>= 1) {
        mn = fminf(mn, __shfl_xor_sync(0xFFFFFFFFu, mn, o));
        mx = fmaxf(mx, __shfl_xor_sync(0xFFFFFFFFu, mx, o));
    }
    if (lane == 0) { red_min[warp] = mn; red_max[warp] = mx; }
    __syncthreads();
    if (tid == 0) {
        float m = red_min[0], M = red_max[0];
        #pragma unroll
        for (int w = 1; w < NWARP; w++) { m = fminf(m, red_min[w]); M = fmaxf(M, red_max[w]); }
        float R = fmaxf(fabsf(m), M);      // range_val = max(|min|, max)
        Rsh = R;
        Ksh = __fdiv_rn(12750.0f, R);      // K: u_i = |x|*K * (1/i)
        if (half == 0) {
            g_aux[0][row] = m;
            g_aux[1][row] = M;
        }
    }
    __syncthreads();
    const float R = Rsh;

    // ---- Phase A2: pre-scale row by K ----
    {
        float Kv = Ksh;
        #pragma unroll
        for (int k = 0; k < 7; k++) {
            int idx = tid + k * THREADS;
            if (idx < N_COLS / 4) {
                float4 v = row4[idx];
                v.x *= Kv; v.y *= Kv; v.z *= Kv; v.w *= Kv;
                row4[idx] = v;
            }
        }
    }

    // ---- Phase B: s2k table for this half's 50 steps ----
    if (tid < HALF_STEPS) {
        int   sg = half * HALF_STEPS + tid;          // global step index 0..99
        float thres = __fdiv_rn(R, 100.0f) * (float)(sg + 1);
        float scale = fmaxf(__fdiv_rn(thres, 127.5f), 1.1920928955078125e-07f);
        s2k[tid] = scale * scale * (1.0f / 8192.0f);
    }
    __syncthreads();

    // ---- Phase C: 5 groups x 10 compile-time steps each ----
    const int grp = tid >> 6;          // 0..4
    const int l64 = tid & 63;
    const float2* row2 = (const float2*)row_sm;
    switch (half * 5 + grp) {
        case 0: run_s0(row2, l64, M2, Mf, warp, lane, partial); break;
        case 1: run_s1(row2, l64, M2, Mf, warp, lane, partial); break;
        case 2: run_s2(row2, l64, M2, Mf, warp, lane, partial); break;
        case 3: run_s3(row2, l64, M2, Mf, warp, lane, partial); break;
        case 4: run_s4(row2, l64, M2, Mf, warp, lane, partial); break;
        case 5: run_s5(row2, l64, M2, Mf, warp, lane, partial); break;
        case 6: run_s6(row2, l64, M2, Mf, warp, lane, partial); break;
        case 7: run_s7(row2, l64, M2, Mf, warp, lane, partial); break;
        case 8: run_s8(row2, l64, M2, Mf, warp, lane, partial); break;
        case 9: run_s9(row2, l64, M2, Mf, warp, lane, partial); break;
    }
    __syncthreads();

    // ---- Phase D: combine warp pairs, write losses to scratch ----
    if (tid < HALF_STEPS) {
        int g  = tid / 10;             // group 0..4
        int jj = tid % 10;             // local step 0..9
        float sum = partial[2 * g][jj] + partial[2 * g + 1][jj];
        g_loss[half * HALF_STEPS + tid][row] = sum * s2k[tid];
    }
}

// Kernel 2: per-row sequential argmin scan (matches lax.scan semantics).
__global__ __launch_bounds__(256)
void mse_argmin_kernel(float* __restrict__ out) {
    int row = blockIdx.x * 256 + threadIdx.x;
    if (row >= N_ROWS) return;
    float rmin = g_aux[0][row];
    float rmax = g_aux[1][row];
    float R = fmaxf(fabsf(rmin), rmax);
    float step_sz = __fdiv_rn(R, 100.0f);      // identical expr to kernel1
    float best = 1.0e9f;
    float bmin = rmin, bmax = rmax;
    for (int j = 0; j < N_STEPS; j++) {
        float L = g_loss[j][row];               // coalesced, L2-hot
        float thres = step_sz * (float)(j + 1);
        if (L < best) { best = L; bmin = -thres; bmax = thres; }
    }
    out[row] = bmin;
    out[N_ROWS + row] = bmax;
}

extern "C" void kernel_launch(void* const* d_in, const int* in_sizes, int n_in,
                              void* d_out, int out_size) {
    const float* x = (const float*)d_in[0];
    float* out = (float*)d_out;
    dim3 grid1(N_ROWS, 2);
    mse_losses_kernel<<<grid1, THREADS>>>(x, 0x4B4000004B400000ULL);
    mse_argmin_kernel<<<N_ROWS / 256, 256>>>(out);
}